// round 6
// baseline (speedup 1.0000x reference)
#include <cuda_runtime.h>
#include <cstdint>

#define NN 50000
#define EE 800000
#define HH 128
#define RR 8

// ---------------- scratch (device globals; no allocation allowed) ----------------
__device__ float g_agg[(size_t)RR * NN * HH];  // [rel][N][128] per-relation neighbor means
__device__ float g_hA[(size_t)NN * HH];
__device__ float g_hB[(size_t)NN * HH];
__device__ int   g_cnt[NN * RR];
__device__ float g_invc[NN * RR];
__device__ int   g_rowptr[NN + 1];
__device__ int   g_beg[NN * RR];
__device__ int   g_cur[NN * RR];
__device__ int   g_ep[EE];            // src node id, CSR-sorted by (dst, etype)
__device__ float g_u[2 * HH];         // column sums of final layer (per graph)

// ---------------- f32x2 packed-FMA helpers ----------------
__device__ __forceinline__ unsigned long long pk2(float lo, float hi) {
    unsigned long long r;
    asm("mov.b64 %0, {%1, %2};" : "=l"(r) : "f"(lo), "f"(hi));
    return r;
}
__device__ __forceinline__ void upk2(unsigned long long v, float& lo, float& hi) {
    asm("mov.b64 {%0, %1}, %2;" : "=f"(lo), "=f"(hi) : "l"(v));
}
__device__ __forceinline__ void fma2(unsigned long long& d, unsigned long long a, unsigned long long b) {
    asm("fma.rn.f32x2 %0, %1, %2, %0;" : "+l"(d) : "l"(a), "l"(b));
}

// ---------------- graph preprocessing ----------------
__global__ void hist_kernel(const int* __restrict__ ei, const int* __restrict__ et) {
    int e = blockIdx.x * blockDim.x + threadIdx.x;
    if (e < EE) {
        int dst = ei[EE + e];
        int r = et[e];
        atomicAdd(&g_cnt[dst * RR + r], 1);
    }
}

// single-block scan over node degrees + per-(node,rel) segment expansion
__global__ void scanexp_kernel() {
    __shared__ int sh[1024];
    __shared__ int s_carry;
    int tid = threadIdx.x;
    if (tid == 0) { s_carry = 0; g_rowptr[0] = 0; }
    __syncthreads();
    for (int base = 0; base < NN; base += 1024) {
        int i = base + tid;
        int cv[RR];
        int v = 0;
        if (i < NN) {
            #pragma unroll
            for (int r = 0; r < RR; r++) { cv[r] = g_cnt[i * RR + r]; v += cv[r]; }
        }
        sh[tid] = v;
        __syncthreads();
        for (int off = 1; off < 1024; off <<= 1) {
            int t = (tid >= off) ? sh[tid - off] : 0;
            __syncthreads();
            sh[tid] += t;
            __syncthreads();
        }
        int incl = sh[tid];
        int c = s_carry;
        if (i < NN) {
            g_rowptr[i + 1] = c + incl;
            int c0 = c + incl - v;            // = rowptr[i]
            #pragma unroll
            for (int r = 0; r < RR; r++) {
                g_beg[i * RR + r] = c0;
                g_cur[i * RR + r] = c0;
                g_invc[i * RR + r] = 1.0f / (float)(cv[r] > 0 ? cv[r] : 1);
                c0 += cv[r];
            }
        }
        __syncthreads();
        if (tid == 0) s_carry = c + sh[1023];
        __syncthreads();
    }
}

__global__ void scatter_kernel(const int* __restrict__ ei, const int* __restrict__ et) {
    int e = blockIdx.x * blockDim.x + threadIdx.x;
    if (e < EE) {
        int comb = ei[EE + e] * RR + et[e];
        int pos = atomicAdd(&g_cur[comb], 1);
        g_ep[pos] = ei[e];
    }
}

// ---------------- aggregation: warp per (rel,node); writes g_agg[rel][N][128] -----
__global__ void agg_kernel(const float* __restrict__ X) {
    int gw = (blockIdx.x * blockDim.x + threadIdx.x) >> 5;
    int lane = threadIdx.x & 31;
    if (gw >= NN * RR) return;
    int rel = gw / NN;
    int node = gw - rel * NN;

    int comb = node * RR + rel;
    int b = g_beg[comb];
    int c = g_cnt[comb];
    float4 a = make_float4(0.f, 0.f, 0.f, 0.f);
    for (int e = b; e < b + c; e++) {
        int src = g_ep[e];
        float4 v = ((const float4*)(X + (size_t)src * HH))[lane];
        a.x += v.x; a.y += v.y; a.z += v.z; a.w += v.w;
    }
    float w = g_invc[comb];
    a.x *= w; a.y *= w; a.z *= w; a.w *= w;
    ((float4*)(g_agg + ((size_t)rel * NN + node) * HH))[lane] = a;
}

// ---------------- GEMM: out[N,128] = sum_r A_r @ W_r + X @ root + bias ------------
// Round-2 proven shape: 256 threads, 128x128 tile, BK=8, col-pair f32x2 accs.
#define BM 128
#define BN 128
#define BK 8
#define GBLK ((NN + BM - 1) / BM)

__global__ __launch_bounds__(256) void gemm_kernel(
    const float* __restrict__ X, const float* __restrict__ W,
    const float* __restrict__ root, const float* __restrict__ bias,
    float* __restrict__ out, int do_relu)
{
    __shared__ float As[BK][BM];
    __shared__ float Bs[BK][BN];

    int tid = threadIdx.x;
    int rowBase = blockIdx.x * BM;
    int aRow = tid >> 1;              // 0..127
    int aCol = (tid & 1) * 4;         // 0 or 4
    int bRow = tid >> 5;              // 0..7
    int bCol = (tid & 31) * 4;        // 0..124

    int tr = (tid >> 4) * 8;          // row offset within tile
    int tc = (tid & 15) * 8;          // col offset within tile

    // acc2[i][jp] holds output cols (tc+2*jp, tc+2*jp+1) for row tr+i
    unsigned long long acc2[8][4];
    #pragma unroll
    for (int i = 0; i < 8; i++)
        #pragma unroll
        for (int j = 0; j < 4; j++) acc2[i][j] = 0ULL;

    for (int rel = 0; rel < 9; rel++) {
        const float* Wp   = (rel < RR) ? (W + (size_t)rel * HH * HH) : root;
        const float* Asrc = (rel < RR) ? (g_agg + (size_t)rel * NN * HH) : X;

        for (int kb = 0; kb < HH; kb += BK) {
            int gm = rowBase + aRow;
            float4 av = make_float4(0.f, 0.f, 0.f, 0.f);
            if (gm < NN) av = *(const float4*)(Asrc + (size_t)gm * HH + kb + aCol);
            As[aCol + 0][aRow] = av.x;
            As[aCol + 1][aRow] = av.y;
            As[aCol + 2][aRow] = av.z;
            As[aCol + 3][aRow] = av.w;

            float4 bv = *(const float4*)(Wp + (size_t)(kb + bRow) * HH + bCol);
            *(float4*)&Bs[bRow][bCol] = bv;
            __syncthreads();

            #pragma unroll
            for (int k = 0; k < BK; k++) {
                float4 a0 = *(const float4*)&As[k][tr];
                float4 a1 = *(const float4*)&As[k][tr + 4];
                float4 b0 = *(const float4*)&Bs[k][tc];
                float4 b1 = *(const float4*)&Bs[k][tc + 4];
                float ra[8] = {a0.x, a0.y, a0.z, a0.w, a1.x, a1.y, a1.z, a1.w};
                unsigned long long bp[4];
                bp[0] = pk2(b0.x, b0.y);
                bp[1] = pk2(b0.z, b0.w);
                bp[2] = pk2(b1.x, b1.y);
                bp[3] = pk2(b1.z, b1.w);
                #pragma unroll
                for (int i = 0; i < 8; i++) {
                    unsigned long long ad = pk2(ra[i], ra[i]);
                    #pragma unroll
                    for (int jp = 0; jp < 4; jp++) fma2(acc2[i][jp], ad, bp[jp]);
                }
            }
            __syncthreads();
        }
    }

    // epilogue: bias, relu, store
    #pragma unroll
    for (int i = 0; i < 8; i++) {
        int gm = rowBase + tr + i;
        if (gm < NN) {
            #pragma unroll
            for (int jp = 0; jp < 2; jp++) {
                float4 o;
                upk2(acc2[i][jp * 2 + 0], o.x, o.y);
                upk2(acc2[i][jp * 2 + 1], o.z, o.w);
                int col = tc + jp * 4;
                o.x += bias[col + 0];
                o.y += bias[col + 1];
                o.z += bias[col + 2];
                o.w += bias[col + 3];
                if (do_relu) {
                    o.x = fmaxf(o.x, 0.f);
                    o.y = fmaxf(o.y, 0.f);
                    o.z = fmaxf(o.z, 0.f);
                    o.w = fmaxf(o.w, 0.f);
                }
                *(float4*)(out + (size_t)gm * HH + col) = o;
            }
        }
    }
}

// ---------------- column sums of final layer output ----------------
__global__ void mean_kernel(const float* __restrict__ X, float* __restrict__ usum) {
    __shared__ float sh[256];
    int tid = threadIdx.x;
    int col = tid & 127;
    int half = tid >> 7;
    int rowsPer = (NN + gridDim.x - 1) / gridDim.x;
    int r0 = blockIdx.x * rowsPer;
    int r1 = min(NN, r0 + rowsPer);
    float local = 0.f;
    for (int r = r0 + half; r < r1; r += 2)
        local += X[(size_t)r * HH + col];
    sh[tid] = local;
    __syncthreads();
    if (tid < 128) atomicAdd(&usum[col], sh[tid] + sh[tid + 128]);
}

// ---------------- final MLP head ----------------
__global__ void fcl_kernel(const float* __restrict__ fc1w, const float* __restrict__ fc1b,
                           const float* __restrict__ fc2w, const float* __restrict__ fc2b,
                           float* __restrict__ out) {
    __shared__ float h[2 * HH];
    __shared__ float red[HH];
    int tid = threadIdx.x;
    if (tid < 2 * HH) h[tid] = g_u[tid] * (1.0f / (float)NN);
    __syncthreads();
    if (tid < HH) {
        float y = fc1b[tid];
        for (int k = 0; k < 2 * HH; k++) y += h[k] * fc1w[k * HH + tid];
        y = fmaxf(y, 0.f);
        red[tid] = y * fc2w[tid];
    }
    __syncthreads();
    for (int off = 64; off > 0; off >>= 1) {
        if (tid < off) red[tid] += red[tid + off];
        __syncthreads();
    }
    if (tid == 0) out[0] = red[0] + fc2b[0];
}

// ---------------- host orchestration ----------------
extern "C" void kernel_launch(void* const* d_in, const int* in_sizes, int n_in,
                              void* d_out, int out_size) {
    const float* x1  = (const float*)d_in[0];
    const int*   ei1 = (const int*)d_in[1];
    const int*   et1 = (const int*)d_in[2];
    const float* x2  = (const float*)d_in[3];
    const int*   ei2 = (const int*)d_in[4];
    const int*   et2 = (const int*)d_in[5];
    const float* Wl[3]    = {(const float*)d_in[6],  (const float*)d_in[9],  (const float*)d_in[12]};
    const float* rootl[3] = {(const float*)d_in[7],  (const float*)d_in[10], (const float*)d_in[13]};
    const float* biasl[3] = {(const float*)d_in[8],  (const float*)d_in[11], (const float*)d_in[14]};
    const float* fc1w = (const float*)d_in[15];
    const float* fc1b = (const float*)d_in[16];
    const float* fc2w = (const float*)d_in[17];
    const float* fc2b = (const float*)d_in[18];

    void *cnt_p, *u_p, *hA_p, *hB_p;
    cudaGetSymbolAddress(&cnt_p, g_cnt);
    cudaGetSymbolAddress(&u_p, g_u);
    cudaGetSymbolAddress(&hA_p, g_hA);
    cudaGetSymbolAddress(&hB_p, g_hB);
    float* hA = (float*)hA_p;
    float* hB = (float*)hB_p;
    float* u  = (float*)u_p;

    const float* xs[2]  = {x1, x2};
    const int*   eis[2] = {ei1, ei2};
    const int*   ets[2] = {et1, et2};

    int aggBlocks = (NN * RR * 32 + 255) / 256;

    // Launch order keeps gemm_kernel at launch #6 so ncu (-s 5 -c 1) profiles it.
    for (int g = 0; g < 2; g++) {
        cudaMemsetAsync(cnt_p, 0, NN * RR * sizeof(int));            // 1
        hist_kernel<<<(EE + 255) / 256, 256>>>(eis[g], ets[g]);      // 2
        scanexp_kernel<<<1, 1024>>>();                               // 3
        scatter_kernel<<<(EE + 255) / 256, 256>>>(eis[g], ets[g]);   // 4

        const float* Xin = xs[g];
        for (int l = 0; l < 3; l++) {
            float* outbuf = (l == 1) ? hB : hA;   // l0->hA, l1->hB, l2->hA
            agg_kernel<<<aggBlocks, 256>>>(Xin);                     // 5
            gemm_kernel<<<GBLK, 256>>>(Xin, Wl[l], rootl[l], biasl[l],
                                       outbuf, (l < 2) ? 1 : 0);     // 6 <- profiled
            Xin = outbuf;
        }
        if (g == 0) cudaMemsetAsync(u_p, 0, 2 * HH * sizeof(float));
        mean_kernel<<<128, 256>>>(Xin, u + g * HH);
    }

    fcl_kernel<<<1, 256>>>(fc1w, fc1b, fc2w, fc2b, (float*)d_out);
}

// round 7
// speedup vs baseline: 2.3150x; 2.3150x over previous
#include <cuda_runtime.h>
#include <cstdint>

#define NN 50000
#define EE 800000
#define HH 128
#define RR 8

// ---------------- scratch (device globals; no allocation allowed) ----------------
__device__ float g_agg[(size_t)RR * NN * HH];  // [rel][N][128] per-relation neighbor means
__device__ float g_hA[(size_t)NN * HH];
__device__ float g_hB[(size_t)NN * HH];
__device__ int   g_cnt[NN * RR];
__device__ float g_invc[NN * RR];
__device__ int   g_rowptr[NN + 1];
__device__ int   g_beg[NN * RR];
__device__ int   g_cur[NN * RR];
__device__ int   g_ep[EE];            // src node id, CSR-sorted by (dst, etype)
__device__ float g_u[2 * HH];         // column sums of final layer (per graph)

// ---------------- tf32 helpers ----------------
__device__ __forceinline__ unsigned cvt_tf32(float v) {
    unsigned r;
    asm("cvt.rna.tf32.f32 %0, %1;" : "=r"(r) : "f"(v));
    return r;
}
__device__ __forceinline__ void mma_tf32(float* c, const unsigned* a, const unsigned* b) {
    asm volatile(
        "mma.sync.aligned.m16n8k8.row.col.f32.tf32.tf32.f32 "
        "{%0,%1,%2,%3}, {%4,%5,%6,%7}, {%8,%9}, {%0,%1,%2,%3};"
        : "+f"(c[0]), "+f"(c[1]), "+f"(c[2]), "+f"(c[3])
        : "r"(a[0]), "r"(a[1]), "r"(a[2]), "r"(a[3]), "r"(b[0]), "r"(b[1]));
}

// ---------------- zero init (kernel, so ncu launch indices are deterministic) -----
__global__ void zero_kernel(int g0) {
    int i = blockIdx.x * blockDim.x + threadIdx.x;
    if (i < NN * RR) g_cnt[i] = 0;
    if (g0 && i < 2 * HH) g_u[i] = 0.f;
}

// ---------------- graph preprocessing ----------------
__global__ void hist_kernel(const int* __restrict__ ei, const int* __restrict__ et) {
    int e = blockIdx.x * blockDim.x + threadIdx.x;
    if (e < EE) {
        int dst = ei[EE + e];
        int r = et[e];
        atomicAdd(&g_cnt[dst * RR + r], 1);
    }
}

// single-block scan over node degrees + per-(node,rel) segment expansion
__global__ void scanexp_kernel() {
    __shared__ int sh[1024];
    __shared__ int s_carry;
    int tid = threadIdx.x;
    if (tid == 0) { s_carry = 0; g_rowptr[0] = 0; }
    __syncthreads();
    for (int base = 0; base < NN; base += 1024) {
        int i = base + tid;
        int cv[RR];
        int v = 0;
        if (i < NN) {
            #pragma unroll
            for (int r = 0; r < RR; r++) { cv[r] = g_cnt[i * RR + r]; v += cv[r]; }
        }
        sh[tid] = v;
        __syncthreads();
        for (int off = 1; off < 1024; off <<= 1) {
            int t = (tid >= off) ? sh[tid - off] : 0;
            __syncthreads();
            sh[tid] += t;
            __syncthreads();
        }
        int incl = sh[tid];
        int c = s_carry;
        if (i < NN) {
            g_rowptr[i + 1] = c + incl;
            int c0 = c + incl - v;            // = rowptr[i]
            #pragma unroll
            for (int r = 0; r < RR; r++) {
                g_beg[i * RR + r] = c0;
                g_cur[i * RR + r] = c0;
                g_invc[i * RR + r] = 1.0f / (float)(cv[r] > 0 ? cv[r] : 1);
                c0 += cv[r];
            }
        }
        __syncthreads();
        if (tid == 0) s_carry = c + sh[1023];
        __syncthreads();
    }
}

__global__ void scatter_kernel(const int* __restrict__ ei, const int* __restrict__ et) {
    int e = blockIdx.x * blockDim.x + threadIdx.x;
    if (e < EE) {
        int comb = ei[EE + e] * RR + et[e];
        int pos = atomicAdd(&g_cur[comb], 1);
        g_ep[pos] = ei[e];
    }
}

// ---------------- aggregation: warp per (rel,node); writes g_agg[rel][N][128] -----
__global__ void agg_kernel(const float* __restrict__ X) {
    int gw = (blockIdx.x * blockDim.x + threadIdx.x) >> 5;
    int lane = threadIdx.x & 31;
    if (gw >= NN * RR) return;
    int rel = gw / NN;
    int node = gw - rel * NN;

    int comb = node * RR + rel;
    int b = g_beg[comb];
    int c = g_cnt[comb];
    float4 a = make_float4(0.f, 0.f, 0.f, 0.f);
    for (int e = b; e < b + c; e++) {
        int src = g_ep[e];
        float4 v = ((const float4*)(X + (size_t)src * HH))[lane];
        a.x += v.x; a.y += v.y; a.z += v.z; a.w += v.w;
    }
    float w = g_invc[comb];
    a.x *= w; a.y *= w; a.z *= w; a.w *= w;
    ((float4*)(g_agg + ((size_t)rel * NN + node) * HH))[lane] = a;
}

// ---------------- tf32 tensor-core GEMM ------------------------------------------
// out[N,128] = sum_r A_r @ W_r + X @ root + bias ; A_r = g_agg[r], K = 9*128.
// CTA: 128x128 tile, 256 threads = 8 warps (4 x 2), warp tile 32x64.
// m16n8k8 tf32 mma, BK=32 chunks, fp32 accumulate.
#define BM 128
#define GBLK ((NN + BM - 1) / BM)
#define APAD 36     // bank map (4g + c): conflict-free
#define BPAD 136    // bank map (8k + g): conflict-free

__global__ __launch_bounds__(256) void gemm_kernel(
    const float* __restrict__ X, const float* __restrict__ W,
    const float* __restrict__ root, const float* __restrict__ bias,
    float* __restrict__ out, int do_relu)
{
    __shared__ float As[128 * APAD];   // 128 rows x 32 k (tf32 bits), pad 36
    __shared__ float Bs[32 * BPAD];    // 32 k x 128 n (tf32 bits), pad 136

    int tid  = threadIdx.x;
    int warp = tid >> 5;
    int lane = tid & 31;
    int gID  = lane >> 2;              // 0..7
    int tig  = lane & 3;               // 0..3
    int wrow = (warp & 3) * 32;
    int wcol = (warp >> 2) * 64;
    int m0   = blockIdx.x * BM;

    float c[2][8][4];
    #pragma unroll
    for (int mt = 0; mt < 2; mt++)
        #pragma unroll
        for (int nt = 0; nt < 8; nt++)
            #pragma unroll
            for (int q = 0; q < 4; q++) c[mt][nt][q] = 0.f;

    for (int rel = 0; rel < 9; rel++) {
        const float* Wp   = (rel < RR) ? (W + (size_t)rel * HH * HH) : root;
        const float* Asrc = (rel < RR) ? (g_agg + (size_t)rel * NN * HH) : X;

        for (int kc = 0; kc < 4; kc++) {
            // stage A: 128 rows x 32 k, cvt to tf32
            #pragma unroll
            for (int it = 0; it < 4; it++) {
                int idx = tid + it * 256;          // 0..1023
                int row = idx >> 3;
                int q   = idx & 7;
                int gm  = m0 + row;
                float4 v = make_float4(0.f, 0.f, 0.f, 0.f);
                if (gm < NN)
                    v = *(const float4*)(Asrc + (size_t)gm * HH + kc * 32 + q * 4);
                uint4 t;
                t.x = cvt_tf32(v.x); t.y = cvt_tf32(v.y);
                t.z = cvt_tf32(v.z); t.w = cvt_tf32(v.w);
                *(uint4*)(As + row * APAD + q * 4) = t;
            }
            // stage B: 32 k x 128 n, cvt to tf32
            #pragma unroll
            for (int it = 0; it < 4; it++) {
                int idx = tid + it * 256;          // 0..1023
                int kr = idx >> 5;
                int nq = (idx & 31) * 4;
                float4 w = *(const float4*)(Wp + (size_t)(kc * 32 + kr) * HH + nq);
                uint4 t;
                t.x = cvt_tf32(w.x); t.y = cvt_tf32(w.y);
                t.z = cvt_tf32(w.z); t.w = cvt_tf32(w.w);
                *(uint4*)(Bs + kr * BPAD + nq) = t;
            }
            __syncthreads();

            #pragma unroll
            for (int ks = 0; ks < 4; ks++) {
                int kb = ks * 8;
                unsigned b[8][2];
                #pragma unroll
                for (int nt = 0; nt < 8; nt++) {
                    int col = wcol + nt * 8 + gID;
                    b[nt][0] = __float_as_uint(Bs[(kb + tig) * BPAD + col]);
                    b[nt][1] = __float_as_uint(Bs[(kb + tig + 4) * BPAD + col]);
                }
                unsigned a[2][4];
                #pragma unroll
                for (int mt = 0; mt < 2; mt++) {
                    int r = wrow + mt * 16 + gID;
                    a[mt][0] = __float_as_uint(As[r * APAD + kb + tig]);
                    a[mt][1] = __float_as_uint(As[(r + 8) * APAD + kb + tig]);
                    a[mt][2] = __float_as_uint(As[r * APAD + kb + tig + 4]);
                    a[mt][3] = __float_as_uint(As[(r + 8) * APAD + kb + tig + 4]);
                }
                #pragma unroll
                for (int mt = 0; mt < 2; mt++)
                    #pragma unroll
                    for (int nt = 0; nt < 8; nt++)
                        mma_tf32(c[mt][nt], a[mt], b[nt]);
            }
            __syncthreads();
        }
    }

    // epilogue: bias, relu, store (frag rows gID / gID+8, cols 2*tig, 2*tig+1)
    #pragma unroll
    for (int mt = 0; mt < 2; mt++) {
        int r0 = m0 + wrow + mt * 16 + gID;
        int r1 = r0 + 8;
        #pragma unroll
        for (int nt = 0; nt < 8; nt++) {
            int col = wcol + nt * 8 + 2 * tig;
            float b0 = bias[col], b1 = bias[col + 1];
            float v0 = c[mt][nt][0] + b0;
            float v1 = c[mt][nt][1] + b1;
            float v2 = c[mt][nt][2] + b0;
            float v3 = c[mt][nt][3] + b1;
            if (do_relu) {
                v0 = fmaxf(v0, 0.f); v1 = fmaxf(v1, 0.f);
                v2 = fmaxf(v2, 0.f); v3 = fmaxf(v3, 0.f);
            }
            if (r0 < NN) *(float2*)(out + (size_t)r0 * HH + col) = make_float2(v0, v1);
            if (r1 < NN) *(float2*)(out + (size_t)r1 * HH + col) = make_float2(v2, v3);
        }
    }
}

// ---------------- column sums of final layer output ----------------
__global__ void mean_kernel(const float* __restrict__ X, float* __restrict__ usum) {
    __shared__ float sh[256];
    int tid = threadIdx.x;
    int col = tid & 127;
    int half = tid >> 7;
    int rowsPer = (NN + gridDim.x - 1) / gridDim.x;
    int r0 = blockIdx.x * rowsPer;
    int r1 = min(NN, r0 + rowsPer);
    float local = 0.f;
    for (int r = r0 + half; r < r1; r += 2)
        local += X[(size_t)r * HH + col];
    sh[tid] = local;
    __syncthreads();
    if (tid < 128) atomicAdd(&usum[col], sh[tid] + sh[tid + 128]);
}

// ---------------- final MLP head ----------------
__global__ void fcl_kernel(const float* __restrict__ fc1w, const float* __restrict__ fc1b,
                           const float* __restrict__ fc2w, const float* __restrict__ fc2b,
                           float* __restrict__ out) {
    __shared__ float h[2 * HH];
    __shared__ float red[HH];
    int tid = threadIdx.x;
    if (tid < 2 * HH) h[tid] = g_u[tid] * (1.0f / (float)NN);
    __syncthreads();
    if (tid < HH) {
        float y = fc1b[tid];
        for (int k = 0; k < 2 * HH; k++) y += h[k] * fc1w[k * HH + tid];
        y = fmaxf(y, 0.f);
        red[tid] = y * fc2w[tid];
    }
    __syncthreads();
    for (int off = 64; off > 0; off >>= 1) {
        if (tid < off) red[tid] += red[tid + off];
        __syncthreads();
    }
    if (tid == 0) out[0] = red[0] + fc2b[0];
}

// ---------------- host orchestration ----------------
extern "C" void kernel_launch(void* const* d_in, const int* in_sizes, int n_in,
                              void* d_out, int out_size) {
    const float* x1  = (const float*)d_in[0];
    const int*   ei1 = (const int*)d_in[1];
    const int*   et1 = (const int*)d_in[2];
    const float* x2  = (const float*)d_in[3];
    const int*   ei2 = (const int*)d_in[4];
    const int*   et2 = (const int*)d_in[5];
    const float* Wl[3]    = {(const float*)d_in[6],  (const float*)d_in[9],  (const float*)d_in[12]};
    const float* rootl[3] = {(const float*)d_in[7],  (const float*)d_in[10], (const float*)d_in[13]};
    const float* biasl[3] = {(const float*)d_in[8],  (const float*)d_in[11], (const float*)d_in[14]};
    const float* fc1w = (const float*)d_in[15];
    const float* fc1b = (const float*)d_in[16];
    const float* fc2w = (const float*)d_in[17];
    const float* fc2b = (const float*)d_in[18];

    void *u_p, *hA_p, *hB_p;
    cudaGetSymbolAddress(&u_p, g_u);
    cudaGetSymbolAddress(&hA_p, g_hA);
    cudaGetSymbolAddress(&hB_p, g_hB);
    float* hA = (float*)hA_p;
    float* hB = (float*)hB_p;
    float* u  = (float*)u_p;

    const float* xs[2]  = {x1, x2};
    const int*   eis[2] = {ei1, ei2};
    const int*   ets[2] = {et1, et2};

    int aggBlocks  = (NN * RR * 32 + 255) / 256;
    int zeroBlocks = (NN * RR + 255) / 256;

    // No memsets anywhere -> launch indices are deterministic:
    // zero(0) hist(1) scanexp(2) scatter(3) agg(4) gemm(5) <- ncu -s 5 profiles gemm
    for (int g = 0; g < 2; g++) {
        zero_kernel<<<zeroBlocks, 256>>>(g == 0 ? 1 : 0);            // 0
        hist_kernel<<<(EE + 255) / 256, 256>>>(eis[g], ets[g]);      // 1
        scanexp_kernel<<<1, 1024>>>();                               // 2
        scatter_kernel<<<(EE + 255) / 256, 256>>>(eis[g], ets[g]);   // 3

        const float* Xin = xs[g];
        for (int l = 0; l < 3; l++) {
            float* outbuf = (l == 1) ? hB : hA;   // l0->hA, l1->hB, l2->hA
            agg_kernel<<<aggBlocks, 256>>>(Xin);                     // 4
            gemm_kernel<<<GBLK, 256>>>(Xin, Wl[l], rootl[l], biasl[l],
                                       outbuf, (l < 2) ? 1 : 0);     // 5 <- profiled
            Xin = outbuf;
        }
        mean_kernel<<<128, 256>>>(Xin, u + g * HH);
    }

    fcl_kernel<<<1, 256>>>(fc1w, fc1b, fc2w, fc2b, (float*)d_out);
}